// round 6
// baseline (speedup 1.0000x reference)
#include <cuda_runtime.h>
#include <math.h>

// ---------------------------------------------------------------------------
// LightGCN fused pipeline:
//   xw = feats @ W                      (k_gemm)
//   h[row] += val * xw[col]  (COO SpMM) (k_spmm, vector f32x4 global reductions)
//   emb = l2norm(tanh(h)); sumsq += ... (k_norm)
//   bpr = sum softplus(-(y_ui - y_uj))  (k_bpr)
//   loss = (bpr + 0.5*wd*sumsq)/B       (k_final)
// Scratch: __device__ globals only (no allocation), single default stream.
// ---------------------------------------------------------------------------

#define NMAX 100000

__device__ float4 g_xw4[NMAX * 16];   // xw, later reused as emb (25.6 MB)
__device__ float4 g_h4[NMAX * 16];    // segment-sum accumulator  (25.6 MB)
__device__ float  g_bpr;
__device__ float  g_sumsq;

// ---------------- init: zero h and accumulators ----------------------------
__global__ void __launch_bounds__(256) k_init(int n16) {
    const float4 z = make_float4(0.f, 0.f, 0.f, 0.f);
    int stride = gridDim.x * blockDim.x;
    for (int i = blockIdx.x * blockDim.x + threadIdx.x; i < n16; i += stride)
        g_h4[i] = z;
    if (blockIdx.x == 0 && threadIdx.x == 0) { g_bpr = 0.f; g_sumsq = 0.f; }
}

// ---------------- GEMM: xw[N,64] = feats[N,256] @ W[256,64] ----------------
// Block = 256 thr = 8 warps. Each block: 32 rows. Warp -> 4 rows, lane -> 2 dims.
// X tile staged in 32 KB smem (broadcast LDS.128); W streamed from L1 (64 KB,
// L1-resident after first pass).
__global__ void __launch_bounds__(256) k_gemm(const float* __restrict__ feats,
                                              const float* __restrict__ W,
                                              int N) {
    __shared__ float sx[32 * 256];
    const int tile = blockIdx.x * 32;

    float4* d4 = (float4*)sx;
    const float4* src = (const float4*)feats + (size_t)tile * 64;
    if (tile + 32 <= N) {
#pragma unroll
        for (int j = 0; j < 8; ++j)
            d4[threadIdx.x + j * 256] = src[threadIdx.x + j * 256];
    } else {
#pragma unroll
        for (int j = 0; j < 8; ++j) {
            int f = threadIdx.x + j * 256;
            int row = tile + (f >> 6);
            float4 v = make_float4(0.f, 0.f, 0.f, 0.f);
            if (row < N) v = src[f];
            d4[f] = v;
        }
    }
    __syncthreads();

    const int warp = threadIdx.x >> 5, lane = threadIdx.x & 31;
    const int r0 = warp * 4, d0 = lane * 2;
    const float* sx0 = sx + r0 * 256;

    float a[4][2] = {{0.f, 0.f}, {0.f, 0.f}, {0.f, 0.f}, {0.f, 0.f}};

    for (int k = 0; k < 256; k += 4) {
        float x0[4], x1[4], x2[4], x3[4];
        *(float4*)x0 = *(const float4*)(sx0 + k);
        *(float4*)x1 = *(const float4*)(sx0 + 256 + k);
        *(float4*)x2 = *(const float4*)(sx0 + 512 + k);
        *(float4*)x3 = *(const float4*)(sx0 + 768 + k);
#pragma unroll
        for (int kk = 0; kk < 4; ++kk) {
            const float2 wv = *(const float2*)(W + (k + kk) * 64 + d0);
            a[0][0] = fmaf(x0[kk], wv.x, a[0][0]); a[0][1] = fmaf(x0[kk], wv.y, a[0][1]);
            a[1][0] = fmaf(x1[kk], wv.x, a[1][0]); a[1][1] = fmaf(x1[kk], wv.y, a[1][1]);
            a[2][0] = fmaf(x2[kk], wv.x, a[2][0]); a[2][1] = fmaf(x2[kk], wv.y, a[2][1]);
            a[3][0] = fmaf(x3[kk], wv.x, a[3][0]); a[3][1] = fmaf(x3[kk], wv.y, a[3][1]);
        }
    }

    float* xw = (float*)g_xw4;
#pragma unroll
    for (int r = 0; r < 4; ++r) {
        int row = tile + r0 + r;
        if (row < N)
            *(float2*)(xw + (size_t)row * 64 + d0) = make_float2(a[r][0], a[r][1]);
    }
}

// ---------------- SpMM scatter: h[row] += val * xw[col] --------------------
// 16 threads per edge, float4 per thread -> one 256B gather + one vector
// red.global.add.v4.f32 per lane (4x fewer L2 atomic ops than scalar).
__global__ void __launch_bounds__(256) k_spmm(const int* __restrict__ erow,
                                              const int* __restrict__ ecol,
                                              const float* __restrict__ evalv,
                                              int E) {
    int t = blockIdx.x * 256 + threadIdx.x;
    int e = t >> 4;
    if (e >= E) return;
    int q = t & 15;
    int r = __ldg(erow + e);
    int c = __ldg(ecol + e);
    float v = __ldg(evalv + e);
    float4 x = g_xw4[(size_t)c * 16 + q];
    float* dst = (float*)(g_h4 + (size_t)r * 16 + q);
    asm volatile("red.global.add.v4.f32 [%0], {%1,%2,%3,%4};"
                 :: "l"(dst), "f"(x.x * v), "f"(x.y * v), "f"(x.z * v), "f"(x.w * v)
                 : "memory");
}

// ---------------- tanh + l2-normalize + sum(emb^2) -------------------------
// Warp per row (64 f32 = 256B coalesced), emb written over g_xw4.
__global__ void __launch_bounds__(256) k_norm(int N) {
    __shared__ float part[8];
    const int gw = (blockIdx.x * 256 + threadIdx.x) >> 5;
    const int lane = threadIdx.x & 31;
    float rowsq = 0.f;
    if (gw < N) {
        const float* h = (const float*)g_h4;
        float2 hv = *(const float2*)(h + (size_t)gw * 64 + lane * 2);
        float tx = tanhf(hv.x), ty = tanhf(hv.y);
        float sq = fmaf(tx, tx, ty * ty);
#pragma unroll
        for (int o = 16; o; o >>= 1) sq += __shfl_xor_sync(0xffffffffu, sq, o);
        float s = rsqrtf(fmaxf(sq, 1e-12f));
        float* emb = (float*)g_xw4;
        *(float2*)(emb + (size_t)gw * 64 + lane * 2) = make_float2(tx * s, ty * s);
        rowsq = sq * s * s;   // == sum(emb_row^2)
    }
    if (lane == 0) part[threadIdx.x >> 5] = rowsq;
    __syncthreads();
    if (threadIdx.x == 0) {
        float s = 0.f;
#pragma unroll
        for (int i = 0; i < 8; ++i) s += part[i];
        atomicAdd(&g_sumsq, s);
    }
}

// ---------------- BPR: sum softplus(-(y_ui - y_uj)) ------------------------
__global__ void __launch_bounds__(256) k_bpr(const int* __restrict__ i1v,
                                             const int* __restrict__ i2v,
                                             const int* __restrict__ inv,
                                             int B) {
    __shared__ float part[8];
    const int gw = (blockIdx.x * 256 + threadIdx.x) >> 5;
    const int lane = threadIdx.x & 31;
    float term = 0.f;
    if (gw < B) {
        const float* emb = (const float*)g_xw4;
        int i1 = __ldg(i1v + gw), i2 = __ldg(i2v + gw), ineg = __ldg(inv + gw);
        float2 o1 = *(const float2*)(emb + (size_t)i1 * 64 + lane * 2);
        float2 o2 = *(const float2*)(emb + (size_t)i2 * 64 + lane * 2);
        float2 on = *(const float2*)(emb + (size_t)ineg * 64 + lane * 2);
        float ui = fmaf(o1.x, o2.x, o1.y * o2.y);
        float uj = fmaf(o1.x, on.x, o1.y * on.y);
#pragma unroll
        for (int o = 16; o; o >>= 1) {
            ui += __shfl_xor_sync(0xffffffffu, ui, o);
            uj += __shfl_xor_sync(0xffffffffu, uj, o);
        }
        float z = uj - ui;  // = -(y_ui - y_uj)
        // -log_sigmoid(d) = softplus(-d) = max(z,0) + log1p(exp(-|z|))
        term = fmaxf(z, 0.f) + log1pf(expf(-fabsf(z)));
    }
    if (lane == 0) part[threadIdx.x >> 5] = term;
    __syncthreads();
    if (threadIdx.x == 0) {
        float s = 0.f;
#pragma unroll
        for (int i = 0; i < 8; ++i) s += part[i];
        atomicAdd(&g_bpr, s);
    }
}

// ---------------- finalize -------------------------------------------------
__global__ void k_final(float* __restrict__ out, float invB) {
    // WEIGHT_DECAY * 0.5 = 1e-4 * 0.5 = 5e-5
    out[0] = (g_bpr + 5e-5f * g_sumsq) * invB;
}

// ---------------------------------------------------------------------------
extern "C" void kernel_launch(void* const* d_in, const int* in_sizes, int n_in,
                              void* d_out, int out_size) {
    const float* feats = (const float*)d_in[0];
    const float* W     = (const float*)d_in[1];
    const int*   erow  = (const int*)d_in[2];
    const int*   ecol  = (const int*)d_in[3];
    const float* evalv = (const float*)d_in[4];
    const int*   idx1  = (const int*)d_in[5];
    const int*   idx2  = (const int*)d_in[6];
    const int*   negi  = (const int*)d_in[7];

    const int N = in_sizes[0] / 256;   // 100000
    const int E = in_sizes[2];         // 3200000
    const int B = in_sizes[5];         // 4096

    k_init<<<2048, 256>>>(N * 16);
    k_gemm<<<(N + 31) / 32, 256>>>(feats, W, N);
    long long spmm_thr = (long long)E * 16;
    k_spmm<<<(int)((spmm_thr + 255) / 256), 256>>>(erow, ecol, evalv, E);
    k_norm<<<(N + 7) / 8, 256>>>(N);
    k_bpr<<<(B + 7) / 8, 256>>>(idx1, idx2, negi, B);
    k_final<<<1, 1>>>((float*)d_out, 1.0f / (float)B);
}

// round 11
// speedup vs baseline: 1.2229x; 1.2229x over previous
#include <cuda_runtime.h>
#include <math.h>

// ---------------------------------------------------------------------------
// LightGCN pipeline v2:
//   Wp   = pack(W even-k, odd-k)                 (k_packW, once per launch)
//   xw   = feats @ W  via fma.rn.f32x2           (k_gemm)
//   CSR build: histogram -> scan -> scatter      (k_zero/k_hist/k_scanA/B/C/k_scatter)
//   h row = sum val*xw[col]; fused tanh+l2norm   (k_csr, warp/row, no atomics on h)
//   bpr   = sum softplus(-(y_ui-y_uj))           (k_bpr)
//   loss  = (bpr + 0.5*wd*sumsq)/B               (k_final)
// ---------------------------------------------------------------------------

#define NMAX 100000
#define EMAX 3200000
#define SCAN_BLK 2048

typedef unsigned long long ull;

__device__ float4 g_xw4[NMAX * 16];    // xw  (25.6 MB)
__device__ float4 g_emb4[NMAX * 16];   // emb (25.6 MB)
__device__ int2   g_scv[EMAX];         // sorted (col, val) pairs (25.6 MB)
__device__ ull    g_Wp[128 * 64];      // packed W: (W[2k][d], W[2k+1][d])
__device__ int    g_cnt[NMAX];
__device__ int    g_rowptr[NMAX + 1];
__device__ int    g_wcur[NMAX];
__device__ int    g_pre[NMAX];
__device__ int    g_bsum[64];
__device__ int    g_boff[64];
__device__ float  g_bpr;
__device__ float  g_sumsq;

// ---- f32x2 helpers --------------------------------------------------------
__device__ __forceinline__ ull pk(float lo, float hi) {
    ull r; asm("mov.b64 %0, {%1,%2};" : "=l"(r) : "f"(lo), "f"(hi)); return r;
}
__device__ __forceinline__ float2 unpk(ull v) {
    float2 f; asm("mov.b64 {%0,%1}, %2;" : "=f"(f.x), "=f"(f.y) : "l"(v)); return f;
}
__device__ __forceinline__ ull f2fma(ull a, ull b, ull c) {
    ull d; asm("fma.rn.f32x2 %0, %1, %2, %3;" : "=l"(d) : "l"(a), "l"(b), "l"(c)); return d;
}

// ---- zero counters + scalars ----------------------------------------------
__global__ void __launch_bounds__(256) k_zero(int N) {
    int i = blockIdx.x * 256 + threadIdx.x;
    if (i < N) g_cnt[i] = 0;
    if (i == 0) { g_bpr = 0.f; g_sumsq = 0.f; }
}

// ---- pack W ---------------------------------------------------------------
__global__ void __launch_bounds__(256) k_packW(const float* __restrict__ W) {
    int idx = blockIdx.x * 256 + threadIdx.x;          // idx = k2*64 + d
    if (idx < 128 * 64) {
        int k2 = idx >> 6, d = idx & 63;
        g_Wp[idx] = pk(W[(2 * k2) * 64 + d], W[(2 * k2 + 1) * 64 + d]);
    }
}

// ---- GEMM: xw[N,64] = feats[N,256] @ W via FFMA2 --------------------------
// Block 256 thr: 32-row X tile in smem. Warp -> 4 rows, lane -> 2 dims.
// Accumulators are f32x2 (even-k, odd-k) partials; Wp pre-packed pairs.
__global__ void __launch_bounds__(256) k_gemm(const float* __restrict__ feats,
                                              int N) {
    __shared__ float sx[32 * 256];
    const int tile = blockIdx.x * 32;

    float4* d4 = (float4*)sx;
    const float4* src = (const float4*)feats + (size_t)tile * 64;
    if (tile + 32 <= N) {
#pragma unroll
        for (int j = 0; j < 8; ++j)
            d4[threadIdx.x + j * 256] = src[threadIdx.x + j * 256];
    } else {
#pragma unroll
        for (int j = 0; j < 8; ++j) {
            int f = threadIdx.x + j * 256;
            int row = tile + (f >> 6);
            float4 v = make_float4(0.f, 0.f, 0.f, 0.f);
            if (row < N) v = src[f];
            d4[f] = v;
        }
    }
    __syncthreads();

    const int warp = threadIdx.x >> 5, lane = threadIdx.x & 31;
    const int r0 = warp * 4, d0 = lane * 2;
    const float* sx0 = sx + r0 * 256;

    ull a00 = 0, a01 = 0, a10 = 0, a11 = 0, a20 = 0, a21 = 0, a30 = 0, a31 = 0;

    for (int k = 0; k < 256; k += 4) {
        float4 x0 = *(const float4*)(sx0 + k);
        float4 x1 = *(const float4*)(sx0 + 256 + k);
        float4 x2 = *(const float4*)(sx0 + 512 + k);
        float4 x3 = *(const float4*)(sx0 + 768 + k);
        const ull* wp = g_Wp + (k >> 1) * 64 + d0;
        ulonglong2 w0 = *(const ulonglong2*)(wp);        // k-pair k/2,   dims d0,d0+1
        ulonglong2 w1 = *(const ulonglong2*)(wp + 64);   // k-pair k/2+1, dims d0,d0+1

        ull p;
        p = pk(x0.x, x0.y); a00 = f2fma(p, w0.x, a00); a01 = f2fma(p, w0.y, a01);
        p = pk(x0.z, x0.w); a00 = f2fma(p, w1.x, a00); a01 = f2fma(p, w1.y, a01);
        p = pk(x1.x, x1.y); a10 = f2fma(p, w0.x, a10); a11 = f2fma(p, w0.y, a11);
        p = pk(x1.z, x1.w); a10 = f2fma(p, w1.x, a10); a11 = f2fma(p, w1.y, a11);
        p = pk(x2.x, x2.y); a20 = f2fma(p, w0.x, a20); a21 = f2fma(p, w0.y, a21);
        p = pk(x2.z, x2.w); a20 = f2fma(p, w1.x, a20); a21 = f2fma(p, w1.y, a21);
        p = pk(x3.x, x3.y); a30 = f2fma(p, w0.x, a30); a31 = f2fma(p, w0.y, a31);
        p = pk(x3.z, x3.w); a30 = f2fma(p, w1.x, a30); a31 = f2fma(p, w1.y, a31);
    }

    float* xw = (float*)g_xw4;
    ull acc[4][2] = {{a00, a01}, {a10, a11}, {a20, a21}, {a30, a31}};
#pragma unroll
    for (int r = 0; r < 4; ++r) {
        int row = tile + r0 + r;
        if (row < N) {
            float2 e0 = unpk(acc[r][0]), e1 = unpk(acc[r][1]);
            *(float2*)(xw + (size_t)row * 64 + d0) =
                make_float2(e0.x + e0.y, e1.x + e1.y);
        }
    }
}

// ---- histogram of edge rows ----------------------------------------------
__global__ void __launch_bounds__(256) k_hist(const int* __restrict__ erow, int E) {
    int e = blockIdx.x * 256 + threadIdx.x;
    if (e < E) atomicAdd(&g_cnt[erow[e]], 1);
}

// ---- scan phase A: per-block (2048-elem) exclusive prescan + block sums ---
__global__ void __launch_bounds__(256) k_scanA(int N) {
    __shared__ int wsum[8];
    __shared__ int wexc[8];
    int base = blockIdx.x * SCAN_BLK + threadIdx.x * 8;
    int vals[8];
    int local = 0;
#pragma unroll
    for (int j = 0; j < 8; ++j) {
        int idx = base + j;
        int c = (idx < N) ? g_cnt[idx] : 0;
        vals[j] = local;
        local += c;
    }
    int lane = threadIdx.x & 31, w = threadIdx.x >> 5;
    int inc = local;
#pragma unroll
    for (int o = 1; o < 32; o <<= 1) {
        int y = __shfl_up_sync(0xffffffffu, inc, o);
        if (lane >= o) inc += y;
    }
    if (lane == 31) wsum[w] = inc;
    __syncthreads();
    if (w == 0 && lane < 8) {
        int v = wsum[lane];
        int s = v;
#pragma unroll
        for (int o = 1; o < 8; o <<= 1) {
            int y = __shfl_up_sync(0x000000ffu, s, o);
            if (lane >= o) s += y;
        }
        wexc[lane] = s - v;
        if (lane == 7) g_bsum[blockIdx.x] = s;
    }
    __syncthreads();
    int toff = wexc[w] + (inc - local);
#pragma unroll
    for (int j = 0; j < 8; ++j) {
        int idx = base + j;
        if (idx < N) g_pre[idx] = toff + vals[j];
    }
}

// ---- scan phase B: exclusive scan of <=64 block sums (1 warp) -------------
__global__ void k_scanB(int nb) {
    int lane = threadIdx.x;
    int v0 = (lane < nb) ? g_bsum[lane] : 0;
    int v1 = (lane + 32 < nb) ? g_bsum[lane + 32] : 0;
    int s0 = v0, s1 = v1;
#pragma unroll
    for (int o = 1; o < 32; o <<= 1) {
        int y0 = __shfl_up_sync(0xffffffffu, s0, o);
        int y1 = __shfl_up_sync(0xffffffffu, s1, o);
        if (lane >= o) { s0 += y0; s1 += y1; }
    }
    int tot0 = __shfl_sync(0xffffffffu, s0, 31);
    if (lane < nb) g_boff[lane] = s0 - v0;
    if (lane + 32 < nb) g_boff[lane + 32] = tot0 + s1 - v1;
}

// ---- scan phase C: finalize rowptr + write cursor -------------------------
__global__ void __launch_bounds__(256) k_scanC(int N, int E) {
    int i = blockIdx.x * 256 + threadIdx.x;
    if (i < N) {
        int v = g_pre[i] + g_boff[i >> 11];
        g_rowptr[i] = v;
        g_wcur[i] = v;
    }
    if (i == N) g_rowptr[N] = E;
}

// ---- scatter edges into CSR order ----------------------------------------
__global__ void __launch_bounds__(256) k_scatter(const int* __restrict__ erow,
                                                 const int* __restrict__ ecol,
                                                 const float* __restrict__ ev,
                                                 int E) {
    int e = blockIdx.x * 256 + threadIdx.x;
    if (e >= E) return;
    int r = erow[e];
    int pos = atomicAdd(&g_wcur[r], 1);
    g_scv[pos] = make_int2(ecol[e], __float_as_int(ev[e]));
}

// ---- CSR SpMM + fused tanh + l2-normalize + sum(emb^2) --------------------
// Warp per row, lane -> 2 dims. Row accumulated in registers (no atomics),
// then the warp normalizes in-place and writes emb once.
__global__ void __launch_bounds__(256) k_csr(int N) {
    __shared__ float part[8];
    const int w = threadIdx.x >> 5, lane = threadIdx.x & 31;
    const int r = blockIdx.x * 8 + w;
    float rowsq = 0.f;
    if (r < N) {
        const int s0 = g_rowptr[r], s1 = g_rowptr[r + 1];
        const float* xw = (const float*)g_xw4;
        float ax = 0.f, ay = 0.f, bx = 0.f, by = 0.f;
        for (int base = s0; base < s1; base += 32) {
            int n = s1 - base; if (n > 32) n = 32;
            int2 cv = make_int2(0, 0);
            if (lane < n) cv = g_scv[base + lane];
            int j = 0;
            for (; j + 1 < n; j += 2) {
                int   c0 = __shfl_sync(0xffffffffu, cv.x, j);
                float v0 = __int_as_float(__shfl_sync(0xffffffffu, cv.y, j));
                int   c1 = __shfl_sync(0xffffffffu, cv.x, j + 1);
                float v1 = __int_as_float(__shfl_sync(0xffffffffu, cv.y, j + 1));
                float2 x0 = *(const float2*)(xw + (size_t)c0 * 64 + lane * 2);
                float2 x1 = *(const float2*)(xw + (size_t)c1 * 64 + lane * 2);
                ax = fmaf(v0, x0.x, ax); ay = fmaf(v0, x0.y, ay);
                bx = fmaf(v1, x1.x, bx); by = fmaf(v1, x1.y, by);
            }
            if (j < n) {
                int   c0 = __shfl_sync(0xffffffffu, cv.x, j);
                float v0 = __int_as_float(__shfl_sync(0xffffffffu, cv.y, j));
                float2 x0 = *(const float2*)(xw + (size_t)c0 * 64 + lane * 2);
                ax = fmaf(v0, x0.x, ax); ay = fmaf(v0, x0.y, ay);
            }
        }
        float tx = tanhf(ax + bx), ty = tanhf(ay + by);
        float sq = fmaf(tx, tx, ty * ty);
#pragma unroll
        for (int o = 16; o; o >>= 1) sq += __shfl_xor_sync(0xffffffffu, sq, o);
        float sc = rsqrtf(fmaxf(sq, 1e-12f));
        float* emb = (float*)g_emb4;
        *(float2*)(emb + (size_t)r * 64 + lane * 2) = make_float2(tx * sc, ty * sc);
        rowsq = sq * sc * sc;           // == sum(emb_row^2)
    }
    if (lane == 0) part[w] = (r < N) ? rowsq : 0.f;
    __syncthreads();
    if (threadIdx.x == 0) {
        float s = 0.f;
#pragma unroll
        for (int i = 0; i < 8; ++i) s += part[i];
        atomicAdd(&g_sumsq, s);
    }
}

// ---- BPR ------------------------------------------------------------------
__global__ void __launch_bounds__(256) k_bpr(const int* __restrict__ i1v,
                                             const int* __restrict__ i2v,
                                             const int* __restrict__ inv,
                                             int B) {
    __shared__ float part[8];
    const int gw = (blockIdx.x * 256 + threadIdx.x) >> 5;
    const int lane = threadIdx.x & 31;
    float term = 0.f;
    if (gw < B) {
        const float* emb = (const float*)g_emb4;
        int i1 = __ldg(i1v + gw), i2 = __ldg(i2v + gw), ineg = __ldg(inv + gw);
        float2 o1 = *(const float2*)(emb + (size_t)i1 * 64 + lane * 2);
        float2 o2 = *(const float2*)(emb + (size_t)i2 * 64 + lane * 2);
        float2 on = *(const float2*)(emb + (size_t)ineg * 64 + lane * 2);
        float ui = fmaf(o1.x, o2.x, o1.y * o2.y);
        float uj = fmaf(o1.x, on.x, o1.y * on.y);
#pragma unroll
        for (int o = 16; o; o >>= 1) {
            ui += __shfl_xor_sync(0xffffffffu, ui, o);
            uj += __shfl_xor_sync(0xffffffffu, uj, o);
        }
        float z = uj - ui;
        term = fmaxf(z, 0.f) + log1pf(expf(-fabsf(z)));
    }
    if (lane == 0) part[threadIdx.x >> 5] = term;
    __syncthreads();
    if (threadIdx.x == 0) {
        float s = 0.f;
#pragma unroll
        for (int i = 0; i < 8; ++i) s += part[i];
        atomicAdd(&g_bpr, s);
    }
}

// ---- finalize -------------------------------------------------------------
__global__ void k_final(float* __restrict__ out, float invB) {
    out[0] = (g_bpr + 5e-5f * g_sumsq) * invB;   // wd*0.5 = 5e-5
}

// ---------------------------------------------------------------------------
extern "C" void kernel_launch(void* const* d_in, const int* in_sizes, int n_in,
                              void* d_out, int out_size) {
    const float* feats = (const float*)d_in[0];
    const float* W     = (const float*)d_in[1];
    const int*   erow  = (const int*)d_in[2];
    const int*   ecol  = (const int*)d_in[3];
    const float* evalv = (const float*)d_in[4];
    const int*   idx1  = (const int*)d_in[5];
    const int*   idx2  = (const int*)d_in[6];
    const int*   negi  = (const int*)d_in[7];

    const int N = in_sizes[0] / 256;   // 100000
    const int E = in_sizes[2];         // 3200000
    const int B = in_sizes[5];         // 4096
    const int nbA = (N + SCAN_BLK - 1) / SCAN_BLK;   // 49

    k_zero<<<(N + 255) / 256, 256>>>(N);
    k_packW<<<32, 256>>>(W);
    k_gemm<<<(N + 31) / 32, 256>>>(feats, N);
    k_hist<<<(E + 255) / 256, 256>>>(erow, E);
    k_scanA<<<nbA, 256>>>(N);
    k_scanB<<<1, 32>>>(nbA);
    k_scanC<<<(N + 1 + 255) / 256, 256>>>(N, E);
    k_scatter<<<(E + 255) / 256, 256>>>(erow, ecol, evalv, E);
    k_csr<<<(N + 7) / 8, 256>>>(N);
    k_bpr<<<(B + 7) / 8, 256>>>(idx1, idx2, negi, B);
    k_final<<<1, 1>>>((float*)d_out, 1.0f / (float)B);
}